// round 16
// baseline (speedup 1.0000x reference)
#include <cuda_runtime.h>
#include <cstdint>

// x: [N=64, C=512, H=56, W=56] fp32. 2:4 structured sparsity along C:
// within each group of 4 channels (same n,h,w), zero the 2 smallest-|x|
// entries (ties: lower channel index dropped first, matching jax top_k).
//
// R16 = R7 (5x-confirmed session best: 121.344us / DRAM ~85% / 6.75 TB/s
// = B300 r+w streaming ceiling) with the last unmeasured load path:
// __ldg (ld.global.nc). x is read-only for the kernel's lifetime, so the
// non-coherent path is legal; it closes the load-policy table
// (plain / .cs / .cg / .nc). Expected neutral; probe only.
//
// Session evidence: R7 config = floor (121.344us x5). Plain loads beat
// .cs (+2.6us) and matched .cg; __stwt stores beat plain/.cs
// (DRAM 83.7->85.4%); MLP=4 beats 8 (occ); fresh-CTA blk256 beats
// persistent (+16%) and blk128/512; guard removal regressed scheduling.

static constexpr int HW4     = (56 * 56) / 4;   // 784 float4 per channel plane
static constexpr int TOTAL_T = 64 * 128 * HW4;  // 6,422,528 (fits int)

// keep element i iff at least 2 of the other 3 are "strictly smaller"
// under less(j,i) = (|a_j| < |a_i|) || (|a_j| == |a_i| && j < i),
// matching jax top_k(-|x|, 2) one-hot drop semantics exactly.
__device__ __forceinline__ void mask4(float& x0, float& x1, float& x2, float& x3) {
    float a0 = fabsf(x0), a1 = fabsf(x1), a2 = fabsf(x2), a3 = fabsf(x3);
    int r0 = 0, r1 = 0, r2 = 0, r3 = 0;
    if (a0 <= a1) r1++; else r0++;   // less(0,1)=a0<=a1 ; less(1,0)=a1<a0
    if (a0 <= a2) r2++; else r0++;
    if (a0 <= a3) r3++; else r0++;
    if (a1 <= a2) r2++; else r1++;
    if (a1 <= a3) r3++; else r1++;
    if (a2 <= a3) r3++; else r2++;
    x0 = (r0 >= 2) ? x0 : 0.0f;
    x1 = (r1 >= 2) ? x1 : 0.0f;
    x2 = (r2 >= 2) ? x2 : 0.0f;
    x3 = (r3 >= 2) ? x3 : 0.0f;
}

__global__ void __launch_bounds__(256, 8)
sparsity24_kernel(const float4* __restrict__ x4, float4* __restrict__ o4) {
    int t = blockIdx.x * 256 + threadIdx.x;
    if (t >= TOTAL_T) return;

    // decode: t -> (ng, hw4); constant divisor -> mul-shift in SASS
    int hw4 = t % HW4;
    int ng  = t / HW4;
    int base = ng * (4 * HW4) + hw4;   // max 25,690,112 < 2^31

    float4 v0 = __ldg(&x4[base]);
    float4 v1 = __ldg(&x4[base + HW4]);
    float4 v2 = __ldg(&x4[base + 2 * HW4]);
    float4 v3 = __ldg(&x4[base + 3 * HW4]);

    mask4(v0.x, v1.x, v2.x, v3.x);
    mask4(v0.y, v1.y, v2.y, v3.y);
    mask4(v0.z, v1.z, v2.z, v3.z);
    mask4(v0.w, v1.w, v2.w, v3.w);

    __stwt(&o4[base],           v0);
    __stwt(&o4[base + HW4],     v1);
    __stwt(&o4[base + 2 * HW4], v2);
    __stwt(&o4[base + 3 * HW4], v3);
}

extern "C" void kernel_launch(void* const* d_in, const int* in_sizes, int n_in,
                              void* d_out, int out_size) {
    const float4* x4 = (const float4*)d_in[0];
    float4* o4 = (float4*)d_out;
    int blocks = (TOTAL_T + 255) / 256;
    sparsity24_kernel<<<blocks, 256>>>(x4, o4);
}

// round 17
// speedup vs baseline: 1.0003x; 1.0003x over previous
#include <cuda_runtime.h>
#include <cstdint>

// x: [N=64, C=512, H=56, W=56] fp32. 2:4 structured sparsity along C:
// within each group of 4 channels (same n,h,w), zero the 2 smallest-|x|
// entries (ties: lower channel index dropped first, matching jax top_k).
//
// FINAL — session optimum, reproduced at 121.344us in SIX independent
// benches (R7/R9/R12/R13/R15/R16). 6.78 TB/s end-to-end = 84.7% of
// 8 TB/s spec — the B300 path-independent read+write streaming ceiling.
// Traffic (822 MB single-touch) is irreducible; compute pipes idle.
//
// Exhaustive 16-round search on GB300 (sm_103a), all axes closed:
//  - one thread per (4-channel group x float4 hw column): 4 coalesced
//    float4 loads strided by the channel plane (per-thread MLP=4),
//    regs=32, occ ~80%. MLP=8/thread (regs 60, occ 40%) regressed 7%.
//  - fresh-CTA launch, block=256. Persistent grid-stride regressed 16%
//    (loop serializes load batches); blocks 128/512 neutral-worse.
//  - load policy: plain == .cg == .nc (all 121.344us); .cs +2.6us.
//  - __stwt write-through stores: output never re-read; skipping L2
//    write-allocate was the only measurable cache-policy win
//    (DRAM 83.7 -> 85.4%).
//  - 32-bit index math (max float4 index 25,690,112 < 2^31); bounds
//    guard kept — removing it worsened ptxas scheduling (R11).

static constexpr int HW4     = (56 * 56) / 4;   // 784 float4 per channel plane
static constexpr int TOTAL_T = 64 * 128 * HW4;  // 6,422,528 (fits int)

// keep element i iff at least 2 of the other 3 are "strictly smaller"
// under less(j,i) = (|a_j| < |a_i|) || (|a_j| == |a_i| && j < i),
// matching jax top_k(-|x|, 2) one-hot drop semantics exactly.
__device__ __forceinline__ void mask4(float& x0, float& x1, float& x2, float& x3) {
    float a0 = fabsf(x0), a1 = fabsf(x1), a2 = fabsf(x2), a3 = fabsf(x3);
    int r0 = 0, r1 = 0, r2 = 0, r3 = 0;
    if (a0 <= a1) r1++; else r0++;   // less(0,1)=a0<=a1 ; less(1,0)=a1<a0
    if (a0 <= a2) r2++; else r0++;
    if (a0 <= a3) r3++; else r0++;
    if (a1 <= a2) r2++; else r1++;
    if (a1 <= a3) r3++; else r1++;
    if (a2 <= a3) r3++; else r2++;
    x0 = (r0 >= 2) ? x0 : 0.0f;
    x1 = (r1 >= 2) ? x1 : 0.0f;
    x2 = (r2 >= 2) ? x2 : 0.0f;
    x3 = (r3 >= 2) ? x3 : 0.0f;
}

__global__ void __launch_bounds__(256, 8)
sparsity24_kernel(const float4* __restrict__ x4, float4* __restrict__ o4) {
    int t = blockIdx.x * 256 + threadIdx.x;
    if (t >= TOTAL_T) return;

    // decode: t -> (ng, hw4); constant divisor -> mul-shift in SASS
    int hw4 = t % HW4;
    int ng  = t / HW4;
    int base = ng * (4 * HW4) + hw4;   // max 25,690,112 < 2^31

    float4 v0 = x4[base];
    float4 v1 = x4[base + HW4];
    float4 v2 = x4[base + 2 * HW4];
    float4 v3 = x4[base + 3 * HW4];

    mask4(v0.x, v1.x, v2.x, v3.x);
    mask4(v0.y, v1.y, v2.y, v3.y);
    mask4(v0.z, v1.z, v2.z, v3.z);
    mask4(v0.w, v1.w, v2.w, v3.w);

    __stwt(&o4[base],           v0);
    __stwt(&o4[base + HW4],     v1);
    __stwt(&o4[base + 2 * HW4], v2);
    __stwt(&o4[base + 3 * HW4], v3);
}

extern "C" void kernel_launch(void* const* d_in, const int* in_sizes, int n_in,
                              void* d_out, int out_size) {
    const float4* x4 = (const float4*)d_in[0];
    float4* o4 = (float4*)d_out;
    int blocks = (TOTAL_T + 255) / 256;
    sparsity24_kernel<<<blocks, 256>>>(x4, o4);
}